// round 4
// baseline (speedup 1.0000x reference)
#include <cuda_runtime.h>
#include <math.h>

#define C_TOT 256
#define C_HID 128
#define HH 512
#define WW 512
#define HW (HH * WW)          // 262144
#define HW4 (HW / 4)          // 65536
#define EPSLN 1e-5f

// Scratch (device globals; no allocation allowed)
__device__ float g_part[C_TOT * 4];       // partial channel sums
__device__ float g_params[2 * C_TOT + 1]; // [0..255]=ch_attn, [256..511]=w_eff, [512]=b_eff

// ---------------------------------------------------------------------------
// Kernel 1: per-channel partial sums of x. grid (256 channels, 4 chunks), 256 thr
// ---------------------------------------------------------------------------
__global__ __launch_bounds__(256) void k_sum(const float* __restrict__ x) {
    const int c = blockIdx.x;
    const int chunk = blockIdx.y;
    const int t = threadIdx.x;
    // each chunk covers HW4/4 = 16384 float4s
    const float4* xp = reinterpret_cast<const float4*>(x)
                     + (size_t)c * HW4 + (size_t)chunk * (HW4 / 4);

    float s = 0.0f;
#pragma unroll 8
    for (int i = t; i < HW4 / 4; i += 256) {
        float4 v = xp[i];
        s += (v.x + v.y) + (v.z + v.w);
    }
    __shared__ float sm[256];
    sm[t] = s;
    __syncthreads();
#pragma unroll
    for (int off = 128; off > 0; off >>= 1) {
        if (t < off) sm[t] += sm[t + off];
        __syncthreads();
    }
    if (t == 0) g_part[c * 4 + chunk] = sm[0];
}

// ---------------------------------------------------------------------------
// Kernel 2: all the tiny math. One block, 256 threads.
// ---------------------------------------------------------------------------
__device__ __forceinline__ float block_reduce_sum(float v, float* red, int t) {
    red[t] = v;
    __syncthreads();
#pragma unroll
    for (int off = 128; off > 0; off >>= 1) {
        if (t < off) red[t] += red[t + off];
        __syncthreads();
    }
    float r = red[0];
    __syncthreads();
    return r;
}

__device__ __forceinline__ float block_reduce_max(float v, float* red, int t) {
    red[t] = v;
    __syncthreads();
#pragma unroll
    for (int off = 128; off > 0; off >>= 1) {
        if (t < off) red[t] = fmaxf(red[t], red[t + off]);
        __syncthreads();
    }
    float r = red[0];
    __syncthreads();
    return r;
}

__global__ __launch_bounds__(256) void k_small(
    const float* __restrict__ ch_cv1_w, const float* __restrict__ ch_cv1_b,
    const float* __restrict__ ch_cv3_w, const float* __restrict__ ch_cv3_b,
    const float* __restrict__ ln_g,     const float* __restrict__ ln_b,
    const float* __restrict__ sp_cv1_w, const float* __restrict__ sp_cv1_b,
    const float* __restrict__ sp_cv2_w, const float* __restrict__ sp_cv2_b)
{
    __shared__ float xsum[C_TOT];
    __shared__ float yv[C_HID];
    __shared__ float s2[C_HID];
    __shared__ float red[C_TOT];

    const int t = threadIdx.x;

    xsum[t] = g_part[t * 4] + g_part[t * 4 + 1] + g_part[t * 4 + 2] + g_part[t * 4 + 3];
    __syncthreads();

    // y = ch_cv1_w @ xsum + HW * ch_cv1_b   (128)
    if (t < C_HID) {
        float a = 0.0f;
#pragma unroll 4
        for (int c = 0; c < C_TOT; c++) a = fmaf(ch_cv1_w[t * C_TOT + c], xsum[c], a);
        yv[t] = a + (float)HW * ch_cv1_b[t];
    }
    __syncthreads();

    // z = ch_cv3_w @ y + ch_cv3_b   (256)
    float z = ch_cv3_b[t];
#pragma unroll 4
    for (int j = 0; j < C_HID; j++) z = fmaf(ch_cv3_w[t * C_HID + j], yv[j], z);

    // LayerNorm over 256 (population variance), then sigmoid -> ch_attn
    float mu = block_reduce_sum(z, red, t) * (1.0f / C_TOT);
    float d = z - mu;
    float var = block_reduce_sum(d * d, red, t) * (1.0f / C_TOT);
    float zn = d * rsqrtf(var + EPSLN);
    float aff = zn * ln_g[t] + ln_b[t];
    g_params[t] = 1.0f / (1.0f + expf(-aff));

    // s2pre = sp_cv2_w @ (xsum/HW) + sp_cv2_b ; softmax over 128
    float s2pre = -INFINITY;
    if (t < C_HID) {
        float a = 0.0f;
#pragma unroll 4
        for (int c = 0; c < C_TOT; c++) a = fmaf(sp_cv2_w[t * C_TOT + c], xsum[c], a);
        s2pre = a * (1.0f / (float)HW) + sp_cv2_b[t];
    }
    float m = block_reduce_max(s2pre, red, t);
    float e = (t < C_HID) ? expf(s2pre - m) : 0.0f;
    float esum = block_reduce_sum(e, red, t);
    if (t < C_HID) s2[t] = e / esum;
    __syncthreads();

    // w_eff[c] = sum_j s2[j] * sp_cv1_w[j, c]
    float we = 0.0f;
#pragma unroll 4
    for (int j = 0; j < C_HID; j++) we = fmaf(s2[j], sp_cv1_w[j * C_TOT + t], we);
    g_params[C_TOT + t] = we;

    // b_eff = dot(s2, sp_cv1_b)
    float bcontrib = (t < C_HID) ? s2[t] * sp_cv1_b[t] : 0.0f;
    float be = block_reduce_sum(bcontrib, red, t);
    if (t == 0) g_params[2 * C_TOT] = be;
}

// ---------------------------------------------------------------------------
// Kernel 3: fused spatial dot + output. Block (32,32), tile = 128 pixels.
// Each thread: 8 channels x float4 (4 pixels) of x held in registers ->
// x read exactly once in this pass. Cross-warp reduction is PARALLEL:
// partials go to 4 planar padded smem arrays (bank-conflict-free), then
// warp ty reduces pixel column ty via shuffle butterfly -- no serial
// single-warp section while 31 warps wait at the barrier.
// ---------------------------------------------------------------------------
__global__ __launch_bounds__(1024, 1) void k_main(const float* __restrict__ x,
                                                  float* __restrict__ out)
{
    __shared__ float s_we[C_TOT];
    __shared__ float s_attn[C_TOT];
    __shared__ float s_ax[32][33];   // [warp(channel grp)][pixel col], padded
    __shared__ float s_ay[32][33];
    __shared__ float s_az[32][33];
    __shared__ float s_aw[32][33];
    __shared__ float4 s_sig[32];

    const int tx = threadIdx.x;      // pixel group within tile
    const int ty = threadIdx.y;      // channel group (== warp id)
    const int t = ty * 32 + tx;

    if (t < C_TOT) {
        s_attn[t] = g_params[t];
        s_we[t]   = g_params[C_TOT + t];
    }
    const float be = g_params[2 * C_TOT];  // uniform scalar, L2-resident
    __syncthreads();

    const float4* x4 = reinterpret_cast<const float4*>(x);
    float4* o4 = reinterpret_cast<float4*>(out);
    const int pos4 = blockIdx.x * 32 + tx;   // float4 index within HW
    const int c0 = ty * 8;

    float4 xv[8];
    float4 acc = make_float4(0.f, 0.f, 0.f, 0.f);
#pragma unroll
    for (int i = 0; i < 8; i++) {
        const int c = c0 + i;
        float4 v = x4[(size_t)c * HW4 + pos4];
        xv[i] = v;
        const float w = s_we[c];
        acc.x = fmaf(w, v.x, acc.x);
        acc.y = fmaf(w, v.y, acc.y);
        acc.z = fmaf(w, v.z, acc.z);
        acc.w = fmaf(w, v.w, acc.w);
    }
    s_ax[ty][tx] = acc.x;
    s_ay[ty][tx] = acc.y;
    s_az[ty][tx] = acc.z;
    s_aw[ty][tx] = acc.w;
    __syncthreads();

    // Warp ty reduces pixel column j = ty: lane tx reads partial from
    // channel-group tx. Bank for s_ax[tx][ty]: (tx*33 + ty) % 32 = (tx+ty)%32
    // -> conflict-free across lanes.
    {
        float ax = s_ax[tx][ty];
        float ay = s_ay[tx][ty];
        float az = s_az[tx][ty];
        float aw = s_aw[tx][ty];
#pragma unroll
        for (int off = 16; off > 0; off >>= 1) {
            ax += __shfl_xor_sync(0xffffffffu, ax, off);
            ay += __shfl_xor_sync(0xffffffffu, ay, off);
            az += __shfl_xor_sync(0xffffffffu, az, off);
            aw += __shfl_xor_sync(0xffffffffu, aw, off);
        }
        if (tx == 0) {
            float4 sg;
            sg.x = 1.0f / (1.0f + __expf(-(ax + be)));
            sg.y = 1.0f / (1.0f + __expf(-(ay + be)));
            sg.z = 1.0f / (1.0f + __expf(-(az + be)));
            sg.w = 1.0f / (1.0f + __expf(-(aw + be)));
            s_sig[ty] = sg;
        }
    }
    __syncthreads();

    const float4 sg = s_sig[tx];
#pragma unroll
    for (int i = 0; i < 8; i++) {
        const int c = c0 + i;
        const float at = s_attn[c];
        float4 v = xv[i];
        float4 o;
        o.x = v.x * (at + sg.x);
        o.y = v.y * (at + sg.y);
        o.z = v.z * (at + sg.z);
        o.w = v.w * (at + sg.w);
        o4[(size_t)c * HW4 + pos4] = o;
    }
}

// ---------------------------------------------------------------------------
extern "C" void kernel_launch(void* const* d_in, const int* in_sizes, int n_in,
                              void* d_out, int out_size) {
    const float* x        = (const float*)d_in[0];
    const float* ch_cv1_w = (const float*)d_in[1];
    const float* ch_cv1_b = (const float*)d_in[2];
    // d_in[3], d_in[4]: ch_cv2_w/b — unused (softmax over size-1 axis == 1)
    const float* ch_cv3_w = (const float*)d_in[5];
    const float* ch_cv3_b = (const float*)d_in[6];
    const float* ln_g     = (const float*)d_in[7];
    const float* ln_b     = (const float*)d_in[8];
    const float* sp_cv1_w = (const float*)d_in[9];
    const float* sp_cv1_b = (const float*)d_in[10];
    const float* sp_cv2_w = (const float*)d_in[11];
    const float* sp_cv2_b = (const float*)d_in[12];
    float* out = (float*)d_out;

    k_sum<<<dim3(C_TOT, 4), 256>>>(x);
    k_small<<<1, 256>>>(ch_cv1_w, ch_cv1_b, ch_cv3_w, ch_cv3_b,
                        ln_g, ln_b, sp_cv1_w, sp_cv1_b, sp_cv2_w, sp_cv2_b);
    k_main<<<HW4 / 32, dim3(32, 32)>>>(x, out);
}